// round 5
// baseline (speedup 1.0000x reference)
#include <cuda_runtime.h>
#include <cuda_bf16.h>
#include <math.h>

#define NNODES 40960
#define NEDGES 163840
#define NGRAPH 1024
typedef unsigned long long ULL;

// padded feature dims (multiples of 16)
#define P1 80
#define P2 160
#define P3 320

// ---------------- static scratch ----------------
__device__ __align__(16) float g_X80[NNODES * P1];
__device__ __align__(16) float g_B1[NNODES * P3];
__device__ __align__(16) float g_B2[NNODES * P3];
__device__ float g_dinv[NNODES];
__device__ int   g_cnt[NNODES];
__device__ int   g_rowptr[NNODES + 1];
__device__ int   g_cur[NNODES];
__device__ int   g_col[NEDGES];
__device__ __align__(16) float g_G[NGRAPH * P3];
__device__ __align__(16) float g_G1[NGRAPH * 1024];
__device__ __align__(16) float g_XC[NGRAPH * 384];
__device__ __align__(16) float g_Y2[NGRAPH * 3872];
__device__ __align__(16) float g_Y1[NGRAPH * 416];
__device__ __align__(16) float g_F1[NGRAPH * 1024];
__device__ __align__(16) float g_F2[NGRAPH * 512];
__device__ __align__(16) float g_Wc2t[750 * 256];
__device__ __align__(16) float g_Wc1t[750 * 256];
__device__ __align__(16) float g_W1p[P1 * P1];
__device__ __align__(16) float g_W2p[P1 * P2];
__device__ __align__(16) float g_W3p[P2 * P3];
__device__ __align__(16) float g_Wg1p[P3 * 1024];
__device__ __align__(16) float g_b1p[P1];
__device__ __align__(16) float g_b2p[P2];
__device__ __align__(16) float g_b3p[P3];

// ---------------- CSR build ----------------
__global__ void k_hist(const int* __restrict__ ei, int* __restrict__ cnt, int e) {
    int i = blockIdx.x * blockDim.x + threadIdx.x;
    if (i < e) atomicAdd(&cnt[ei[e + i]], 1);
}
__global__ void k_scan(const int* __restrict__ cnt, int* __restrict__ rowptr,
                       int* __restrict__ cur, float* __restrict__ dinv) {
    __shared__ int ssum[1024];
    int t = threadIdx.x;
    const int CH = NNODES / 1024;
    int base = t * CH;
    int s = 0;
    for (int i = 0; i < CH; i++) s += cnt[base + i];
    ssum[t] = s;
    __syncthreads();
    for (int off = 1; off < 1024; off <<= 1) {
        int v = (t >= off) ? ssum[t - off] : 0;
        __syncthreads();
        ssum[t] += v;
        __syncthreads();
    }
    int run = ssum[t] - s;
    for (int i = 0; i < CH; i++) {
        int c = cnt[base + i];
        rowptr[base + i] = run;
        cur[base + i]    = run;
        dinv[base + i]   = rsqrtf((float)c + 1.0f);
        run += c;
    }
    if (t == 1023) rowptr[NNODES] = run;
}
__global__ void k_scatter(const int* __restrict__ ei, int* __restrict__ cur,
                          int* __restrict__ col, int e) {
    int i = blockIdx.x * blockDim.x + threadIdx.x;
    if (i >= e) return;
    int s = ei[i], d = ei[e + i];
    int pos = atomicAdd(&cur[d], 1);
    col[pos] = s;
}

// ---------------- padding kernels ----------------
__global__ void k_padx(const float* __restrict__ x, const float* __restrict__ dinv,
                       float4* __restrict__ xp) {
    int t = blockIdx.x * blockDim.x + threadIdx.x;
    if (t >= NNODES * (P1 / 4)) return;
    int node = t / (P1 / 4), c = t - node * (P1 / 4);
    float di = dinv[node];
    float4 v;
    int f = c * 4;
    v.x = (f + 0 < 78) ? di * x[(size_t)node * 78 + f + 0] : 0.f;
    v.y = (f + 1 < 78) ? di * x[(size_t)node * 78 + f + 1] : 0.f;
    v.z = (f + 2 < 78) ? di * x[(size_t)node * 78 + f + 2] : 0.f;
    v.w = (f + 3 < 78) ? di * x[(size_t)node * 78 + f + 3] : 0.f;
    xp[t] = v;
}
__global__ void k_padw(const float* __restrict__ W, float* __restrict__ Wp,
                       int K, int N, int Kp, int Np) {
    int t = blockIdx.x * blockDim.x + threadIdx.x;
    if (t >= Kp * Np) return;
    int k = t / Np, n = t - k * Np;
    Wp[t] = (k < K && n < N) ? W[(size_t)k * N + n] : 0.f;
}
__global__ void k_fillbias(float* __restrict__ C, const float* __restrict__ b,
                           int M, int N, int ldc, int coff) {
    int t = blockIdx.x * blockDim.x + threadIdx.x;
    if (t >= M * N) return;
    int m = t / N, n = t - m * N;
    C[(size_t)m * ldc + coff + n] = b[n];
}

// ---------------- packed-f32x2 GEMM, m-pair scheme -----------------------
// tile 128m x 64n, 128 threads (ty 8 x tx 16), micro 16m(8 pairs) x 4n
// acc[p][j]: lo = C[m0], hi = C[m0+1] where m0 = bm + ty*16 + 2p, n = bn + tx*4 + j
__device__ __forceinline__ void fma2(ULL& d, ULL a, ULL b) {
    asm("fma.rn.f32x2 %0, %1, %2, %0;" : "+l"(d) : "l"(a), "l"(b));
}
__device__ __forceinline__ ULL dup2(float x) {
    ULL r; unsigned xi = __float_as_uint(x);
    asm("mov.b64 %0, {%1, %1};" : "=l"(r) : "r"(xi));
    return r;
}
__global__ void __launch_bounds__(128)
k_gemm(const float* __restrict__ A, const float* __restrict__ B,
       float* __restrict__ C, int M, int N, int K, int lda,
       const float* __restrict__ bias, const float* __restrict__ rs,
       int relu, int ldc, int coff, int Kc, int split,
       const int* __restrict__ bat) {
    __shared__ __align__(16) float As[16][128];
    __shared__ __align__(16) float Bs[16][64];
    int tid = threadIdx.x;
    int tx = tid & 15, ty = tid >> 4;
    int bm = blockIdx.y * 128, bn = blockIdx.x * 64;
    int kbeg = blockIdx.z * Kc, kend = min(K, kbeg + Kc);
    ULL acc[8][4];
#pragma unroll
    for (int p = 0; p < 8; p++)
#pragma unroll
        for (int j = 0; j < 4; j++) acc[p][j] = 0ULL;

    const float* arow = A + (size_t)(bm + tid) * lda;
    float4 ra[4], rb[2];

    // preload first k-tile
#pragma unroll
    for (int i = 0; i < 4; i++) ra[i] = *(const float4*)&arow[kbeg + i * 4];
#pragma unroll
    for (int l = 0; l < 2; l++) {
        int q = tid + l * 128;
        int kq = q >> 4, n4 = q & 15;
        int n = bn + n4 * 4;
        rb[l] = (n < N) ? *(const float4*)&B[(size_t)(kbeg + kq) * N + n]
                        : make_float4(0.f, 0.f, 0.f, 0.f);
    }

    for (int k0 = kbeg; k0 < kend; k0 += 16) {
        // commit staged regs to smem
#pragma unroll
        for (int i = 0; i < 4; i++) {
            As[i * 4 + 0][tid] = ra[i].x;
            As[i * 4 + 1][tid] = ra[i].y;
            As[i * 4 + 2][tid] = ra[i].z;
            As[i * 4 + 3][tid] = ra[i].w;
        }
#pragma unroll
        for (int l = 0; l < 2; l++) {
            int q = tid + l * 128;
            int kq = q >> 4, n4 = q & 15;
            *(float4*)&Bs[kq][n4 * 4] = rb[l];
        }
        __syncthreads();
        int k1 = k0 + 16;
        if (k1 < kend) {
#pragma unroll
            for (int i = 0; i < 4; i++) ra[i] = *(const float4*)&arow[k1 + i * 4];
#pragma unroll
            for (int l = 0; l < 2; l++) {
                int q = tid + l * 128;
                int kq = q >> 4, n4 = q & 15;
                int n = bn + n4 * 4;
                rb[l] = (n < N) ? *(const float4*)&B[(size_t)(k1 + kq) * N + n]
                                : make_float4(0.f, 0.f, 0.f, 0.f);
            }
        }
#pragma unroll
        for (int kk = 0; kk < 16; kk++) {
            ULL a2[8];
#pragma unroll
            for (int q = 0; q < 4; q++) {
                ulonglong2 t = *(ulonglong2*)&As[kk][ty * 16 + q * 4];
                a2[q * 2] = t.x; a2[q * 2 + 1] = t.y;
            }
            float4 bv = *(float4*)&Bs[kk][tx * 4];
            ULL b2[4];
            b2[0] = dup2(bv.x); b2[1] = dup2(bv.y);
            b2[2] = dup2(bv.z); b2[3] = dup2(bv.w);
#pragma unroll
            for (int p = 0; p < 8; p++)
#pragma unroll
                for (int j = 0; j < 4; j++) fma2(acc[p][j], a2[p], b2[j]);
        }
        __syncthreads();
    }

    // epilogue
#pragma unroll
    for (int p = 0; p < 8; p++) {
        int m0 = bm + ty * 16 + p * 2;
        float s0 = rs ? rs[m0] : 1.f;
        float s1 = rs ? rs[m0 + 1] : 1.f;
        int pr0 = bat ? bat[m0] : 0;
        int pr1 = bat ? bat[m0 + 1] : 0;
#pragma unroll
        for (int j = 0; j < 4; j++) {
            int n = bn + tx * 4 + j;
            if (n >= N) continue;
            float2 v = *(float2*)&acc[p][j];   // v.x -> m0, v.y -> m0+1
            if (split) {
                atomicAdd(&C[(size_t)m0 * ldc + coff + n],       v.x);
                atomicAdd(&C[(size_t)(m0 + 1) * ldc + coff + n], v.y);
            } else if (bat) {
                float bn_ = bias ? bias[n] : 0.f;
                float o0 = fmaxf(v.x + bn_, 0.f);
                float o1 = fmaxf(v.y + bn_, 0.f);
                atomicMax((int*)&C[(size_t)pr0 * ldc + n], __float_as_int(o0));
                atomicMax((int*)&C[(size_t)pr1 * ldc + n], __float_as_int(o1));
            } else {
                float bn_ = bias ? bias[n] : 0.f;
                float o0 = v.x + bn_, o1 = v.y + bn_;
                if (relu) { o0 = fmaxf(o0, 0.f); o1 = fmaxf(o1, 0.f); }
                o0 *= s0; o1 *= s1;
                C[(size_t)m0 * ldc + coff + n]       = o0;
                C[(size_t)(m0 + 1) * ldc + coff + n] = o1;
            }
        }
    }
}

// ---------------- CSR gather: out[d] = dinv[d] * (h'[d] + sum_nbr h'[s]) -----
__global__ void k_aggr4(const float4* __restrict__ hws, const int* __restrict__ rowptr,
                        const int* __restrict__ col, const float* __restrict__ dinv,
                        float4* __restrict__ outp, int ld4) {
    int t = blockIdx.x * blockDim.x + threadIdx.x;
    if (t >= NNODES * ld4) return;
    int node = t / ld4, c = t - node * ld4;
    float4 acc = hws[(size_t)node * ld4 + c];
    int re = rowptr[node + 1];
    for (int e = rowptr[node]; e < re; e++) {
        float4 v = hws[(size_t)col[e] * ld4 + c];
        acc.x += v.x; acc.y += v.y; acc.z += v.z; acc.w += v.w;
    }
    float di = dinv[node];
    outp[(size_t)node * ld4 + c] = make_float4(acc.x * di, acc.y * di, acc.z * di, acc.w * di);
}

// ---------------- transpose Wc[32][750][8] -> Wt[750][256] -------------------
__global__ void k_transw(const float* __restrict__ W, float* __restrict__ Wt) {
    int i = blockIdx.x * blockDim.x + threadIdx.x;
    if (i >= 750 * 256) return;
    int c = i >> 8, ok = i & 255;
    int o = ok >> 3, k = ok & 7;
    Wt[i] = W[((size_t)o * 750 + c) * 8 + k];
}

// ---------------- protein branch 2: 2 graphs per block, dynamic smem ---------
__global__ void k_branch2(const int* __restrict__ t2, const float* __restrict__ Wc2t,
                          const float* __restrict__ embw, const float* __restrict__ bc2,
                          float* __restrict__ Y2) {
    extern __shared__ float sm2[];
    float* Tl0  = sm2;                       // 26*256
    float* Tl1  = sm2 + 6656;                // 26*256
    float* embs = sm2 + 2 * 6656;            // 26*128
    int*   t2s  = (int*)(sm2 + 2 * 6656 + 3328);   // 2*750
    int b0 = blockIdx.x * 2, tid = threadIdx.x;
    for (int i = tid; i < 6656; i += 256) { Tl0[i] = 0.f; Tl1[i] = 0.f; }
    for (int i = tid; i < 3328; i += 256) embs[i] = embw[i];
    for (int i = tid; i < 1500; i += 256) t2s[i] = t2[(size_t)b0 * 750 + i];
    __syncthreads();
    for (int c = 0; c < 750; c++) {
        float w = Wc2t[(size_t)c * 256 + tid];
        Tl0[t2s[c] * 256 + tid]       += w;
        Tl1[t2s[750 + c] * 256 + tid] += w;
    }
    __syncthreads();
    for (int g = 0; g < 2; g++) {
        const float* Tl = g ? Tl1 : Tl0;
        for (int idx = tid; idx < 32 * 121; idx += 256) {
            int o = idx / 121, l = idx - o * 121;
            float acc = bc2[o];
            for (int v = 0; v < 26; v++) {
#pragma unroll
                for (int k = 0; k < 8; k++)
                    acc += Tl[v * 256 + o * 8 + k] * embs[v * 128 + l + k];
            }
            Y2[(size_t)(b0 + g) * 3872 + idx] = acc;
        }
    }
}

// ---------------- protein branch 1: direct conv, 4 graphs per block ----------
__global__ void k_conv1(const float* __restrict__ t1, const float* __restrict__ Wc1t,
                        const float* __restrict__ bc1, float* __restrict__ Y1) {
    __shared__ float sin_[4][1000];
    int b0 = blockIdx.x * 4, tid = threadIdx.x;
    int o = tid >> 3, k = tid & 7;
    float acc[4][13] = {};
    for (int c0 = 0; c0 < 750; c0 += 50) {
#pragma unroll
        for (int g = 0; g < 4; g++)
            for (int i = tid; i < 1000; i += 256)
                sin_[g][i] = t1[(size_t)(b0 + g) * 15000 + c0 * 20 + i];
        __syncthreads();
        for (int cc = 0; cc < 50; cc++) {
            float w = Wc1t[(size_t)(c0 + cc) * 256 + tid];
#pragma unroll
            for (int g = 0; g < 4; g++)
#pragma unroll
                for (int l = 0; l < 13; l++)
                    acc[g][l] += w * sin_[g][cc * 20 + k + l];
        }
        __syncthreads();
    }
#pragma unroll
    for (int g = 0; g < 4; g++)
#pragma unroll
        for (int l = 0; l < 13; l++) {
            float v = acc[g][l];
            v += __shfl_down_sync(0xffffffffu, v, 4, 8);
            v += __shfl_down_sync(0xffffffffu, v, 2, 8);
            v += __shfl_down_sync(0xffffffffu, v, 1, 8);
            if (k == 0) Y1[(size_t)(b0 + g) * 416 + o * 13 + l] = v + bc1[o];
        }
}

// ---------------- final projection -------------------------------------------
__global__ void k_out(const float* __restrict__ F2w, const float* __restrict__ Wo,
                      const float* __restrict__ bo, float* __restrict__ out) {
    int warp = (blockIdx.x * blockDim.x + threadIdx.x) >> 5;
    int lane = threadIdx.x & 31;
    if (warp >= NGRAPH) return;
    float s = 0.f;
    for (int i = lane; i < 512; i += 32) s += F2w[(size_t)warp * 512 + i] * Wo[i];
#pragma unroll
    for (int off = 16; off; off >>= 1) s += __shfl_down_sync(0xffffffffu, s, off);
    if (lane == 0) out[warp] = s + bo[0];
}

// ---------------- host orchestration ----------------
extern "C" void kernel_launch(void* const* d_in, const int* in_sizes, int n_in,
                              void* d_out, int out_size) {
    const float* x   = (const float*)d_in[0];
    const int*   ei  = (const int*)  d_in[1];
    const int*   bat = (const int*)  d_in[2];
    const float* t1  = (const float*)d_in[3];
    const int*   t2  = (const int*)  d_in[4];
    const float *W1 = (const float*)d_in[5],  *b1 = (const float*)d_in[6];
    const float *W2 = (const float*)d_in[7],  *b2 = (const float*)d_in[8];
    const float *W3 = (const float*)d_in[9],  *b3 = (const float*)d_in[10];
    const float *Wg1= (const float*)d_in[11], *bg1= (const float*)d_in[12];
    const float *Wg2= (const float*)d_in[13], *bg2= (const float*)d_in[14];
    const float *emb= (const float*)d_in[15];
    const float *Wc2= (const float*)d_in[16], *bc2= (const float*)d_in[17];
    const float *Wxt2=(const float*)d_in[18], *bxt2=(const float*)d_in[19];
    const float *Wc1= (const float*)d_in[20], *bc1= (const float*)d_in[21];
    const float *Wxt1=(const float*)d_in[22], *bxt1=(const float*)d_in[23];
    const float *Wf1= (const float*)d_in[24], *bf1= (const float*)d_in[25];
    const float *Wf2= (const float*)d_in[26], *bf2= (const float*)d_in[27];
    const float *Wo = (const float*)d_in[28], *bo = (const float*)d_in[29];
    float* out = (float*)d_out;

    float *X80, *B1, *B2, *dinv, *G, *G1, *XC, *Y2, *Y1, *Fb1, *Fb2, *Wc2t, *Wc1t;
    float *W1p, *W2p, *W3p, *Wg1p, *b1p, *b2p, *b3p;
    int *cnt, *rowptr, *cur, *col;
    cudaGetSymbolAddress((void**)&X80, g_X80);
    cudaGetSymbolAddress((void**)&B1, g_B1);
    cudaGetSymbolAddress((void**)&B2, g_B2);
    cudaGetSymbolAddress((void**)&dinv, g_dinv);
    cudaGetSymbolAddress((void**)&cnt, g_cnt);
    cudaGetSymbolAddress((void**)&rowptr, g_rowptr);
    cudaGetSymbolAddress((void**)&cur, g_cur);
    cudaGetSymbolAddress((void**)&col, g_col);
    cudaGetSymbolAddress((void**)&G, g_G);
    cudaGetSymbolAddress((void**)&G1, g_G1);
    cudaGetSymbolAddress((void**)&XC, g_XC);
    cudaGetSymbolAddress((void**)&Y2, g_Y2);
    cudaGetSymbolAddress((void**)&Y1, g_Y1);
    cudaGetSymbolAddress((void**)&Fb1, g_F1);
    cudaGetSymbolAddress((void**)&Fb2, g_F2);
    cudaGetSymbolAddress((void**)&Wc2t, g_Wc2t);
    cudaGetSymbolAddress((void**)&Wc1t, g_Wc1t);
    cudaGetSymbolAddress((void**)&W1p, g_W1p);
    cudaGetSymbolAddress((void**)&W2p, g_W2p);
    cudaGetSymbolAddress((void**)&W3p, g_W3p);
    cudaGetSymbolAddress((void**)&Wg1p, g_Wg1p);
    cudaGetSymbolAddress((void**)&b1p, g_b1p);
    cudaGetSymbolAddress((void**)&b2p, g_b2p);
    cudaGetSymbolAddress((void**)&b3p, g_b3p);

    cudaFuncSetAttribute(k_branch2, cudaFuncAttributeMaxDynamicSharedMemorySize, 73000);

    const int N = NNODES, E = NEDGES;

    // ---- launches 1-5 (prep), slot 6 = k_aggr4 L1 for ncu ----
    cudaMemsetAsync(cnt, 0, N * sizeof(int));                       // 1
    k_hist   <<<(E + 255) / 256, 256>>>(ei, cnt, E);                // 2
    k_scan   <<<1, 1024>>>(cnt, rowptr, cur, dinv);                 // 3
    k_scatter<<<(E + 255) / 256, 256>>>(ei, cur, col, E);           // 4
    k_padx   <<<(N * (P1/4) + 255) / 256, 256>>>(x, dinv, (float4*)X80); // 5
    k_aggr4<<<(N*(P1/4) + 255)/256, 256>>>((float4*)X80, rowptr, col, dinv, (float4*)B1, P1/4); // 6

    // remaining prep
    k_padw   <<<(P1*P1 + 255) / 256, 256>>>(W1, W1p, 78, 78, P1, P1);
    k_padw   <<<(P1*P2 + 255) / 256, 256>>>(W2, W2p, 78, 156, P1, P2);
    k_padw   <<<(P2*P3 + 255) / 256, 256>>>(W3, W3p, 156, 312, P2, P3);
    k_padw   <<<(P3*1024 + 255) / 256, 256>>>(Wg1, Wg1p, 312, 1024, P3, 1024);
    k_padw   <<<1, P1>>>(b1, b1p, 1, 78, 1, P1);
    k_padw   <<<1, P2>>>(b2, b2p, 1, 156, 1, P2);
    k_padw   <<<1, P3>>>(b3, b3p, 1, 312, 1, P3);
    cudaMemsetAsync(G, 0, (size_t)NGRAPH * P3 * sizeof(float));

    // ---- GCN: aggregate-then-GEMM, h' = dinv*relu(a@W + b) ----
    k_gemm<<<dim3(2, N/128, 1), 128>>>(B1, W1p, B2, N, P1, P1, P1, b1p, dinv, 1, P1, 0, P1, 0, nullptr);
    k_aggr4<<<(N*(P1/4) + 255)/256, 256>>>((float4*)B2, rowptr, col, dinv, (float4*)B1, P1/4);
    k_gemm<<<dim3(3, N/128, 1), 128>>>(B1, W2p, B2, N, P2, P1, P1, b2p, dinv, 1, P2, 0, P1, 0, nullptr);
    k_aggr4<<<(N*(P2/4) + 255)/256, 256>>>((float4*)B2, rowptr, col, dinv, (float4*)B1, P2/4);
    // layer 3: GEMM with fused relu + per-graph max-pool into G
    k_gemm<<<dim3(5, N/128, 1), 128>>>(B1, W3p, G, N, P3, P2, P2, b3p, nullptr, 1, P3, 0, P2, 0, bat);

    // ---- graph head ----
    k_gemm<<<dim3(16, 8, 1), 128>>>(G, Wg1p, G1, NGRAPH, 1024, P3, P3, bg1, nullptr, 1, 1024, 0, P3, 0, nullptr);
    k_fillbias<<<(NGRAPH*128 + 255)/256, 256>>>(XC, bg2, NGRAPH, 128, 384, 0);
    k_gemm<<<dim3(2, 8, 8), 128>>>(G1, Wg2, XC, NGRAPH, 128, 1024, 1024, nullptr, nullptr, 0, 384, 0, 128, 1, nullptr);

    // ---- protein branch 2 -> XC[:,256:384] ----
    k_transw<<<750, 256>>>(Wc2, Wc2t);
    k_branch2<<<NGRAPH/2, 256, 73000>>>(t2, Wc2t, emb, bc2, Y2);
    k_fillbias<<<(NGRAPH*128 + 255)/256, 256>>>(XC, bxt2, NGRAPH, 128, 384, 256);
    k_gemm<<<dim3(2, 8, 11), 128>>>(Y2, Wxt2, XC, NGRAPH, 128, 3872, 3872, nullptr, nullptr, 0, 384, 256, 352, 1, nullptr);

    // ---- protein branch 1 -> XC[:,128:256] ----
    k_transw<<<750, 256>>>(Wc1, Wc1t);
    k_conv1<<<NGRAPH/4, 256>>>(t1, Wc1t, bc1, Y1);
    k_fillbias<<<(NGRAPH*128 + 255)/256, 256>>>(XC, bxt1, NGRAPH, 128, 384, 128);
    k_gemm<<<dim3(2, 8, 4), 128>>>(Y1, Wxt1, XC, NGRAPH, 128, 416, 416, nullptr, nullptr, 0, 384, 128, 112, 1, nullptr);

    // ---- fusion head ----
    k_gemm<<<dim3(16, 8, 1), 128>>>(XC, Wf1, Fb1, NGRAPH, 1024, 384, 384, bf1, nullptr, 1, 1024, 0, 384, 0, nullptr);
    k_gemm<<<dim3(8, 8, 1), 128>>>(Fb1, Wf2, Fb2, NGRAPH, 512, 1024, 1024, bf2, nullptr, 1, 512, 0, 1024, 0, nullptr);
    k_out<<<(NGRAPH * 32 + 255) / 256, 256>>>(Fb2, Wo, bo, out);
}

// round 6
// speedup vs baseline: 1.3200x; 1.3200x over previous
#include <cuda_runtime.h>
#include <cuda_bf16.h>
#include <math.h>

#define NNODES 40960
#define NEDGES 163840
#define NGRAPH 1024
typedef unsigned long long ULL;

// padded feature dims (multiples of 16)
#define P1 80
#define P2 160
#define P3 320

// ---------------- static scratch ----------------
__device__ __align__(16) float g_X80[NNODES * P1];
__device__ __align__(16) float g_B1[NNODES * P3];
__device__ __align__(16) float g_B2[NNODES * P3];
__device__ float g_dinv[NNODES];
__device__ int   g_cnt[NNODES];
__device__ int   g_rowptr[NNODES + 1];
__device__ int   g_cur[NNODES];
__device__ int   g_col[NEDGES];
__device__ __align__(16) float g_G[NGRAPH * P3];
__device__ __align__(16) float g_G1[NGRAPH * 1024];
__device__ __align__(16) float g_XC[NGRAPH * 384];
__device__ __align__(16) float g_Y2[NGRAPH * 3872];
__device__ __align__(16) float g_Y1[NGRAPH * 416];
__device__ __align__(16) float g_F1[NGRAPH * 1024];
__device__ __align__(16) float g_F2[NGRAPH * 512];
__device__ __align__(16) float g_Wc2t[750 * 256];
__device__ __align__(16) float g_Wc1t[750 * 256];
__device__ __align__(16) float g_W1p[P1 * P1];
__device__ __align__(16) float g_W2p[P1 * P2];
__device__ __align__(16) float g_W3p[P2 * P3];
__device__ __align__(16) float g_Wg1p[P3 * 1024];
__device__ __align__(16) float g_b1p[P1];
__device__ __align__(16) float g_b2p[P2];
__device__ __align__(16) float g_b3p[P3];

// ---------------- CSR build ----------------
__global__ void k_hist(const int* __restrict__ ei, int* __restrict__ cnt, int e) {
    int i = blockIdx.x * blockDim.x + threadIdx.x;
    if (i < e) atomicAdd(&cnt[ei[e + i]], 1);
}
__global__ void k_scan(const int* __restrict__ cnt, int* __restrict__ rowptr,
                       int* __restrict__ cur, float* __restrict__ dinv) {
    __shared__ int ssum[1024];
    int t = threadIdx.x;
    const int CH = NNODES / 1024;
    int base = t * CH;
    int s = 0;
    for (int i = 0; i < CH; i++) s += cnt[base + i];
    ssum[t] = s;
    __syncthreads();
    for (int off = 1; off < 1024; off <<= 1) {
        int v = (t >= off) ? ssum[t - off] : 0;
        __syncthreads();
        ssum[t] += v;
        __syncthreads();
    }
    int run = ssum[t] - s;
    for (int i = 0; i < CH; i++) {
        int c = cnt[base + i];
        rowptr[base + i] = run;
        cur[base + i]    = run;
        dinv[base + i]   = rsqrtf((float)c + 1.0f);
        run += c;
    }
    if (t == 1023) rowptr[NNODES] = run;
}
__global__ void k_scatter(const int* __restrict__ ei, int* __restrict__ cur,
                          int* __restrict__ col, int e) {
    int i = blockIdx.x * blockDim.x + threadIdx.x;
    if (i >= e) return;
    int s = ei[i], d = ei[e + i];
    int pos = atomicAdd(&cur[d], 1);
    col[pos] = s;
}

// ---------------- padding kernels ----------------
__global__ void k_padx(const float* __restrict__ x, const float* __restrict__ dinv,
                       float4* __restrict__ xp) {
    int t = blockIdx.x * blockDim.x + threadIdx.x;
    if (t >= NNODES * (P1 / 4)) return;
    int node = t / (P1 / 4), c = t - node * (P1 / 4);
    float di = dinv[node];
    float4 v;
    int f = c * 4;
    v.x = (f + 0 < 78) ? di * x[(size_t)node * 78 + f + 0] : 0.f;
    v.y = (f + 1 < 78) ? di * x[(size_t)node * 78 + f + 1] : 0.f;
    v.z = (f + 2 < 78) ? di * x[(size_t)node * 78 + f + 2] : 0.f;
    v.w = (f + 3 < 78) ? di * x[(size_t)node * 78 + f + 3] : 0.f;
    xp[t] = v;
}
__global__ void k_padw(const float* __restrict__ W, float* __restrict__ Wp,
                       int K, int N, int Kp, int Np) {
    int t = blockIdx.x * blockDim.x + threadIdx.x;
    if (t >= Kp * Np) return;
    int k = t / Np, n = t - k * Np;
    Wp[t] = (k < K && n < N) ? W[(size_t)k * N + n] : 0.f;
}
__global__ void k_fillbias(float* __restrict__ C, const float* __restrict__ b,
                           int M, int N, int ldc, int coff) {
    int t = blockIdx.x * blockDim.x + threadIdx.x;
    if (t >= M * N) return;
    int m = t / N, n = t - m * N;
    C[(size_t)m * ldc + coff + n] = b[n];
}

// ---------------- packed-f32x2 GEMM, m-pair scheme -----------------------
__device__ __forceinline__ void fma2(ULL& d, ULL a, ULL b) {
    asm("fma.rn.f32x2 %0, %1, %2, %0;" : "+l"(d) : "l"(a), "l"(b));
}
__device__ __forceinline__ ULL dup2(float x) {
    ULL r; unsigned xi = __float_as_uint(x);
    asm("mov.b64 %0, {%1, %1};" : "=l"(r) : "r"(xi));
    return r;
}
__global__ void __launch_bounds__(128)
k_gemm(const float* __restrict__ A, const float* __restrict__ B,
       float* __restrict__ C, int M, int N, int K, int lda,
       const float* __restrict__ bias, const float* __restrict__ rs,
       int relu, int ldc, int coff, int Kc, int split,
       const int* __restrict__ bat) {
    __shared__ __align__(16) float As[16][128];
    __shared__ __align__(16) float Bs[16][64];
    int tid = threadIdx.x;
    int tx = tid & 15, ty = tid >> 4;
    int bm = blockIdx.y * 128, bn = blockIdx.x * 64;
    int kbeg = blockIdx.z * Kc, kend = min(K, kbeg + Kc);
    ULL acc[8][4];
#pragma unroll
    for (int p = 0; p < 8; p++)
#pragma unroll
        for (int j = 0; j < 4; j++) acc[p][j] = 0ULL;

    const float* arow = A + (size_t)(bm + tid) * lda;
    float4 ra[4], rb[2];

#pragma unroll
    for (int i = 0; i < 4; i++) ra[i] = *(const float4*)&arow[kbeg + i * 4];
#pragma unroll
    for (int l = 0; l < 2; l++) {
        int q = tid + l * 128;
        int kq = q >> 4, n4 = q & 15;
        int n = bn + n4 * 4;
        rb[l] = (n < N) ? *(const float4*)&B[(size_t)(kbeg + kq) * N + n]
                        : make_float4(0.f, 0.f, 0.f, 0.f);
    }

    for (int k0 = kbeg; k0 < kend; k0 += 16) {
#pragma unroll
        for (int i = 0; i < 4; i++) {
            As[i * 4 + 0][tid] = ra[i].x;
            As[i * 4 + 1][tid] = ra[i].y;
            As[i * 4 + 2][tid] = ra[i].z;
            As[i * 4 + 3][tid] = ra[i].w;
        }
#pragma unroll
        for (int l = 0; l < 2; l++) {
            int q = tid + l * 128;
            int kq = q >> 4, n4 = q & 15;
            *(float4*)&Bs[kq][n4 * 4] = rb[l];
        }
        __syncthreads();
        int k1 = k0 + 16;
        if (k1 < kend) {
#pragma unroll
            for (int i = 0; i < 4; i++) ra[i] = *(const float4*)&arow[k1 + i * 4];
#pragma unroll
            for (int l = 0; l < 2; l++) {
                int q = tid + l * 128;
                int kq = q >> 4, n4 = q & 15;
                int n = bn + n4 * 4;
                rb[l] = (n < N) ? *(const float4*)&B[(size_t)(k1 + kq) * N + n]
                                : make_float4(0.f, 0.f, 0.f, 0.f);
            }
        }
#pragma unroll
        for (int kk = 0; kk < 16; kk++) {
            ULL a2[8];
#pragma unroll
            for (int q = 0; q < 4; q++) {
                ulonglong2 t = *(ulonglong2*)&As[kk][ty * 16 + q * 4];
                a2[q * 2] = t.x; a2[q * 2 + 1] = t.y;
            }
            float4 bv = *(float4*)&Bs[kk][tx * 4];
            ULL b2[4];
            b2[0] = dup2(bv.x); b2[1] = dup2(bv.y);
            b2[2] = dup2(bv.z); b2[3] = dup2(bv.w);
#pragma unroll
            for (int p = 0; p < 8; p++)
#pragma unroll
                for (int j = 0; j < 4; j++) fma2(acc[p][j], a2[p], b2[j]);
        }
        __syncthreads();
    }

#pragma unroll
    for (int p = 0; p < 8; p++) {
        int m0 = bm + ty * 16 + p * 2;
        float s0 = rs ? rs[m0] : 1.f;
        float s1 = rs ? rs[m0 + 1] : 1.f;
        int pr0 = bat ? bat[m0] : 0;
        int pr1 = bat ? bat[m0 + 1] : 0;
#pragma unroll
        for (int j = 0; j < 4; j++) {
            int n = bn + tx * 4 + j;
            if (n >= N) continue;
            float2 v = *(float2*)&acc[p][j];
            if (split) {
                atomicAdd(&C[(size_t)m0 * ldc + coff + n],       v.x);
                atomicAdd(&C[(size_t)(m0 + 1) * ldc + coff + n], v.y);
            } else if (bat) {
                float bn_ = bias ? bias[n] : 0.f;
                float o0 = fmaxf(v.x + bn_, 0.f);
                float o1 = fmaxf(v.y + bn_, 0.f);
                atomicMax((int*)&C[(size_t)pr0 * ldc + n], __float_as_int(o0));
                atomicMax((int*)&C[(size_t)pr1 * ldc + n], __float_as_int(o1));
            } else {
                float bn_ = bias ? bias[n] : 0.f;
                float o0 = v.x + bn_, o1 = v.y + bn_;
                if (relu) { o0 = fmaxf(o0, 0.f); o1 = fmaxf(o1, 0.f); }
                o0 *= s0; o1 *= s1;
                C[(size_t)m0 * ldc + coff + n]       = o0;
                C[(size_t)(m0 + 1) * ldc + coff + n] = o1;
            }
        }
    }
}

// ---------------- CSR gather ----------------
__global__ void k_aggr4(const float4* __restrict__ hws, const int* __restrict__ rowptr,
                        const int* __restrict__ col, const float* __restrict__ dinv,
                        float4* __restrict__ outp, int ld4) {
    int t = blockIdx.x * blockDim.x + threadIdx.x;
    if (t >= NNODES * ld4) return;
    int node = t / ld4, c = t - node * ld4;
    float4 acc = hws[(size_t)node * ld4 + c];
    int re = rowptr[node + 1];
    for (int e = rowptr[node]; e < re; e++) {
        float4 v = hws[(size_t)col[e] * ld4 + c];
        acc.x += v.x; acc.y += v.y; acc.z += v.z; acc.w += v.w;
    }
    float di = dinv[node];
    outp[(size_t)node * ld4 + c] = make_float4(acc.x * di, acc.y * di, acc.z * di, acc.w * di);
}

// ---------------- transpose Wc[32][750][8] -> Wt[750][256] -------------------
__global__ void k_transw(const float* __restrict__ W, float* __restrict__ Wt) {
    int i = blockIdx.x * blockDim.x + threadIdx.x;
    if (i >= 750 * 256) return;
    int c = i >> 8, ok = i & 255;
    int o = ok >> 3, k = ok & 7;
    Wt[i] = W[((size_t)o * 750 + c) * 8 + k];
}

// ---------------- protein branch 2: 2 graphs per block, dynamic smem ---------
__global__ void k_branch2(const int* __restrict__ t2, const float* __restrict__ Wc2t,
                          const float* __restrict__ embw, const float* __restrict__ bc2,
                          float* __restrict__ Y2) {
    extern __shared__ float sm2[];
    float* Tl0  = sm2;
    float* Tl1  = sm2 + 6656;
    float* embs = sm2 + 2 * 6656;
    int*   t2s  = (int*)(sm2 + 2 * 6656 + 3328);
    int b0 = blockIdx.x * 2, tid = threadIdx.x;
    for (int i = tid; i < 6656; i += 256) { Tl0[i] = 0.f; Tl1[i] = 0.f; }
    for (int i = tid; i < 3328; i += 256) embs[i] = embw[i];
    for (int i = tid; i < 1500; i += 256) t2s[i] = t2[(size_t)b0 * 750 + i];
    __syncthreads();
    for (int c = 0; c < 750; c++) {
        float w = Wc2t[(size_t)c * 256 + tid];
        Tl0[t2s[c] * 256 + tid]       += w;
        Tl1[t2s[750 + c] * 256 + tid] += w;
    }
    __syncthreads();
    for (int g = 0; g < 2; g++) {
        const float* Tl = g ? Tl1 : Tl0;
        for (int idx = tid; idx < 32 * 121; idx += 256) {
            int o = idx / 121, l = idx - o * 121;
            float acc = bc2[o];
            for (int v = 0; v < 26; v++) {
#pragma unroll
                for (int k = 0; k < 8; k++)
                    acc += Tl[v * 256 + o * 8 + k] * embs[v * 128 + l + k];
            }
            Y2[(size_t)(b0 + g) * 3872 + idx] = acc;
        }
    }
}

// ---------------- protein branch 1: direct conv, 4 graphs per block ----------
__global__ void k_conv1(const float* __restrict__ t1, const float* __restrict__ Wc1t,
                        const float* __restrict__ bc1, float* __restrict__ Y1) {
    __shared__ float sin_[4][1000];
    int b0 = blockIdx.x * 4, tid = threadIdx.x;
    int o = tid >> 3, k = tid & 7;
    float acc[4][13] = {};
    for (int c0 = 0; c0 < 750; c0 += 50) {
#pragma unroll
        for (int g = 0; g < 4; g++)
            for (int i = tid; i < 1000; i += 256)
                sin_[g][i] = t1[(size_t)(b0 + g) * 15000 + c0 * 20 + i];
        __syncthreads();
        for (int cc = 0; cc < 50; cc++) {
            float w = Wc1t[(size_t)(c0 + cc) * 256 + tid];
#pragma unroll
            for (int g = 0; g < 4; g++)
#pragma unroll
                for (int l = 0; l < 13; l++)
                    acc[g][l] += w * sin_[g][cc * 20 + k + l];
        }
        __syncthreads();
    }
#pragma unroll
    for (int g = 0; g < 4; g++)
#pragma unroll
        for (int l = 0; l < 13; l++) {
            float v = acc[g][l];
            v += __shfl_down_sync(0xffffffffu, v, 4, 8);
            v += __shfl_down_sync(0xffffffffu, v, 2, 8);
            v += __shfl_down_sync(0xffffffffu, v, 1, 8);
            if (k == 0) Y1[(size_t)(b0 + g) * 416 + o * 13 + l] = v + bc1[o];
        }
}

// ---------------- final projection -------------------------------------------
__global__ void k_out(const float* __restrict__ F2w, const float* __restrict__ Wo,
                      const float* __restrict__ bo, float* __restrict__ out) {
    int warp = (blockIdx.x * blockDim.x + threadIdx.x) >> 5;
    int lane = threadIdx.x & 31;
    if (warp >= NGRAPH) return;
    float s = 0.f;
    for (int i = lane; i < 512; i += 32) s += F2w[(size_t)warp * 512 + i] * Wo[i];
#pragma unroll
    for (int off = 16; off; off >>= 1) s += __shfl_down_sync(0xffffffffu, s, off);
    if (lane == 0) out[warp] = s + bo[0];
}

// ---------------- host orchestration ----------------
extern "C" void kernel_launch(void* const* d_in, const int* in_sizes, int n_in,
                              void* d_out, int out_size) {
    const float* x   = (const float*)d_in[0];
    const int*   ei  = (const int*)  d_in[1];
    const int*   bat = (const int*)  d_in[2];
    const float* t1  = (const float*)d_in[3];
    const int*   t2  = (const int*)  d_in[4];
    const float *W1 = (const float*)d_in[5],  *b1 = (const float*)d_in[6];
    const float *W2 = (const float*)d_in[7],  *b2 = (const float*)d_in[8];
    const float *W3 = (const float*)d_in[9],  *b3 = (const float*)d_in[10];
    const float *Wg1= (const float*)d_in[11], *bg1= (const float*)d_in[12];
    const float *Wg2= (const float*)d_in[13], *bg2= (const float*)d_in[14];
    const float *emb= (const float*)d_in[15];
    const float *Wc2= (const float*)d_in[16], *bc2= (const float*)d_in[17];
    const float *Wxt2=(const float*)d_in[18], *bxt2=(const float*)d_in[19];
    const float *Wc1= (const float*)d_in[20], *bc1= (const float*)d_in[21];
    const float *Wxt1=(const float*)d_in[22], *bxt1=(const float*)d_in[23];
    const float *Wf1= (const float*)d_in[24], *bf1= (const float*)d_in[25];
    const float *Wf2= (const float*)d_in[26], *bf2= (const float*)d_in[27];
    const float *Wo = (const float*)d_in[28], *bo = (const float*)d_in[29];
    float* out = (float*)d_out;

    float *X80, *B1, *B2, *dinv, *G, *G1, *XC, *Y2, *Y1, *Fb1, *Fb2, *Wc2t, *Wc1t;
    float *W1p, *W2p, *W3p, *Wg1p, *b1p, *b2p, *b3p;
    int *cnt, *rowptr, *cur, *col;
    cudaGetSymbolAddress((void**)&X80, g_X80);
    cudaGetSymbolAddress((void**)&B1, g_B1);
    cudaGetSymbolAddress((void**)&B2, g_B2);
    cudaGetSymbolAddress((void**)&dinv, g_dinv);
    cudaGetSymbolAddress((void**)&cnt, g_cnt);
    cudaGetSymbolAddress((void**)&rowptr, g_rowptr);
    cudaGetSymbolAddress((void**)&cur, g_cur);
    cudaGetSymbolAddress((void**)&col, g_col);
    cudaGetSymbolAddress((void**)&G, g_G);
    cudaGetSymbolAddress((void**)&G1, g_G1);
    cudaGetSymbolAddress((void**)&XC, g_XC);
    cudaGetSymbolAddress((void**)&Y2, g_Y2);
    cudaGetSymbolAddress((void**)&Y1, g_Y1);
    cudaGetSymbolAddress((void**)&Fb1, g_F1);
    cudaGetSymbolAddress((void**)&Fb2, g_F2);
    cudaGetSymbolAddress((void**)&Wc2t, g_Wc2t);
    cudaGetSymbolAddress((void**)&Wc1t, g_Wc1t);
    cudaGetSymbolAddress((void**)&W1p, g_W1p);
    cudaGetSymbolAddress((void**)&W2p, g_W2p);
    cudaGetSymbolAddress((void**)&W3p, g_W3p);
    cudaGetSymbolAddress((void**)&Wg1p, g_Wg1p);
    cudaGetSymbolAddress((void**)&b1p, g_b1p);
    cudaGetSymbolAddress((void**)&b2p, g_b2p);
    cudaGetSymbolAddress((void**)&b3p, g_b3p);

    cudaFuncSetAttribute(k_branch2, cudaFuncAttributeMaxDynamicSharedMemorySize, 73000);

    const int N = NNODES, E = NEDGES;

    // ---- fork side streams for the protein branches ----
    cudaStream_t sB, sC;
    cudaEvent_t evFork, evB, evC;
    cudaStreamCreateWithFlags(&sB, cudaStreamNonBlocking);
    cudaStreamCreateWithFlags(&sC, cudaStreamNonBlocking);
    cudaEventCreateWithFlags(&evFork, cudaEventDisableTiming);
    cudaEventCreateWithFlags(&evB, cudaEventDisableTiming);
    cudaEventCreateWithFlags(&evC, cudaEventDisableTiming);

    cudaEventRecord(evFork, 0);
    cudaStreamWaitEvent(sB, evFork, 0);
    cudaStreamWaitEvent(sC, evFork, 0);

    // ===== stream B: protein branch 2 -> XC[:,256:384] =====
    k_transw<<<750, 256, 0, sB>>>(Wc2, Wc2t);
    k_branch2<<<NGRAPH/2, 256, 73000, sB>>>(t2, Wc2t, emb, bc2, Y2);
    k_fillbias<<<(NGRAPH*128 + 255)/256, 256, 0, sB>>>(XC, bxt2, NGRAPH, 128, 384, 256);
    k_gemm<<<dim3(2, 8, 11), 128, 0, sB>>>(Y2, Wxt2, XC, NGRAPH, 128, 3872, 3872, nullptr, nullptr, 0, 384, 256, 352, 1, nullptr);
    cudaEventRecord(evB, sB);

    // ===== stream C: protein branch 1 -> XC[:,128:256] =====
    k_transw<<<750, 256, 0, sC>>>(Wc1, Wc1t);
    k_conv1<<<NGRAPH/4, 256, 0, sC>>>(t1, Wc1t, bc1, Y1);
    k_fillbias<<<(NGRAPH*128 + 255)/256, 256, 0, sC>>>(XC, bxt1, NGRAPH, 128, 384, 128);
    k_gemm<<<dim3(2, 8, 4), 128, 0, sC>>>(Y1, Wxt1, XC, NGRAPH, 128, 416, 416, nullptr, nullptr, 0, 384, 128, 112, 1, nullptr);
    cudaEventRecord(evC, sC);

    // ===== default stream: GCN chain =====
    cudaMemsetAsync(cnt, 0, N * sizeof(int));
    k_hist   <<<(E + 255) / 256, 256>>>(ei, cnt, E);
    k_scan   <<<1, 1024>>>(cnt, rowptr, cur, dinv);
    k_scatter<<<(E + 255) / 256, 256>>>(ei, cur, col, E);
    k_padx   <<<(N * (P1/4) + 255) / 256, 256>>>(x, dinv, (float4*)X80);
    k_aggr4<<<(N*(P1/4) + 255)/256, 256>>>((float4*)X80, rowptr, col, dinv, (float4*)B1, P1/4);

    k_padw   <<<(P1*P1 + 255) / 256, 256>>>(W1, W1p, 78, 78, P1, P1);
    k_padw   <<<(P1*P2 + 255) / 256, 256>>>(W2, W2p, 78, 156, P1, P2);
    k_padw   <<<(P2*P3 + 255) / 256, 256>>>(W3, W3p, 156, 312, P2, P3);
    k_padw   <<<(P3*1024 + 255) / 256, 256>>>(Wg1, Wg1p, 312, 1024, P3, 1024);
    k_padw   <<<1, P1>>>(b1, b1p, 1, 78, 1, P1);
    k_padw   <<<1, P2>>>(b2, b2p, 1, 156, 1, P2);
    k_padw   <<<1, P3>>>(b3, b3p, 1, 312, 1, P3);
    cudaMemsetAsync(G, 0, (size_t)NGRAPH * P3 * sizeof(float));

    k_gemm<<<dim3(2, N/128, 1), 128>>>(B1, W1p, B2, N, P1, P1, P1, b1p, dinv, 1, P1, 0, P1, 0, nullptr);
    k_aggr4<<<(N*(P1/4) + 255)/256, 256>>>((float4*)B2, rowptr, col, dinv, (float4*)B1, P1/4);
    k_gemm<<<dim3(3, N/128, 1), 128>>>(B1, W2p, B2, N, P2, P1, P1, b2p, dinv, 1, P2, 0, P1, 0, nullptr);
    k_aggr4<<<(N*(P2/4) + 255)/256, 256>>>((float4*)B2, rowptr, col, dinv, (float4*)B1, P2/4);
    k_gemm<<<dim3(5, N/128, 1), 128>>>(B1, W3p, G, N, P3, P2, P2, b3p, nullptr, 1, P3, 0, P2, 0, bat);

    // ---- graph head -> XC[:,0:128] ----
    k_gemm<<<dim3(16, 8, 1), 128>>>(G, Wg1p, G1, NGRAPH, 1024, P3, P3, bg1, nullptr, 1, 1024, 0, P3, 0, nullptr);
    k_fillbias<<<(NGRAPH*128 + 255)/256, 256>>>(XC, bg2, NGRAPH, 128, 384, 0);
    k_gemm<<<dim3(2, 8, 8), 128>>>(G1, Wg2, XC, NGRAPH, 128, 1024, 1024, nullptr, nullptr, 0, 384, 0, 128, 1, nullptr);

    // ---- join branches, then fusion head ----
    cudaStreamWaitEvent(0, evB, 0);
    cudaStreamWaitEvent(0, evC, 0);
    k_gemm<<<dim3(16, 8, 1), 128>>>(XC, Wf1, Fb1, NGRAPH, 1024, 384, 384, bf1, nullptr, 1, 1024, 0, 384, 0, nullptr);
    k_gemm<<<dim3(8, 8, 1), 128>>>(Fb1, Wf2, Fb2, NGRAPH, 512, 1024, 1024, bf2, nullptr, 1, 512, 0, 1024, 0, nullptr);
    k_out<<<(NGRAPH * 32 + 255) / 256, 256>>>(Fb2, Wo, bo, out);

    // cleanup only when not capturing (during capture these stay alive in the graph)
    cudaStreamCaptureStatus cap = cudaStreamCaptureStatusNone;
    cudaStreamIsCapturing(0, &cap);
    if (cap == cudaStreamCaptureStatusNone) {
        cudaStreamDestroy(sB);
        cudaStreamDestroy(sC);
        cudaEventDestroy(evFork);
        cudaEventDestroy(evB);
        cudaEventDestroy(evC);
    }
}